// round 4
// baseline (speedup 1.0000x reference)
#include <cuda_runtime.h>
#include <cuda_fp16.h>

// NeRF volume-rendering aggregation — R4.
// R3 hung: divergent __shfl_sync inside `if (lane==31)` (UB -> warp hang).
// Fixed: boundary broadcasts execute convergently on all lanes; lane 31
// merely selects the value. Rest of R3 unchanged:
//  - rgb sigmoids via tanh.approx.f16x2 (MUFU/pt 4 -> 2.5)
//  - z[p+1] via shfl_down instead of a second LDG

#define FARV 1e10f
#define EPSV 1e-10f
#define FULL 0xffffffffu

__device__ __forceinline__ __half2 h2_tanh(__half2 x) {
    __half2 r;
    asm("tanh.approx.f16x2 %0, %1;" : "=r"(*(unsigned*)&r) : "r"(*(unsigned*)&x));
    return r;
}

__global__ __launch_bounds__(256) void nerf_agg_kernel(
    const float4* __restrict__ raw,    // (NR, 128) of float4
    const float*  __restrict__ z,      // (NR, 128)
    const float*  __restrict__ rays_d, // (NR, 3)
    const float*  __restrict__ bg,     // (3)
    float* __restrict__ out_rgb,       // (NR, 3)
    float* __restrict__ out_depth,     // (NR)
    float* __restrict__ out_disp,      // (NR)
    float* __restrict__ out_alpha,     // (NR)
    float* __restrict__ out_w,         // (NR, 128)
    int nrays)
{
    const int warp = threadIdx.x >> 5;
    const int lane = threadIdx.x & 31;
    const int ray  = blockIdx.x * 8 + warp;
    if (ray >= nrays) return;   // warp-uniform exit

    const float4* rawr = raw + (size_t)ray * 128;
    const float*  zr   = z   + (size_t)ray * 128;

    // ray-direction norm (lane-uniform broadcast loads)
    const float dx = rays_d[ray * 3 + 0];
    const float dy = rays_d[ray * 3 + 1];
    const float dz = rays_d[ray * 3 + 2];
    const float nrm = sqrtf(dx * dx + dy * dy + dz * dz);

    // ---- Phase A: batched loads (max MLP) ----
    float4 rv[4];
    float  zp[4];
#pragma unroll
    for (int rr = 0; rr < 4; rr++) {
        const int p = rr * 32 + lane;
        rv[rr] = rawr[p];
        zp[rr] = zr[p];
    }

    // next-sample depth via shuffles (no extra LDGs).
    // ALL shuffles execute convergently; lane 31 only SELECTS the boundary value.
    float zn[4];
#pragma unroll
    for (int rr = 0; rr < 4; rr++)
        zn[rr] = __shfl_down_sync(FULL, zp[rr], 1);   // lane31 result garbage, fixed below
    {
        const float h1 = __shfl_sync(FULL, zp[1], 0); // convergent broadcasts
        const float h2 = __shfl_sync(FULL, zp[2], 0);
        const float h3 = __shfl_sync(FULL, zp[3], 0);
        if (lane == 31) { zn[0] = h1; zn[1] = h2; zn[2] = h3; }
        // zn[3]@lane31 unused (p==127 -> FAR)
    }

    // ---- Phase B: alpha (f32 EX2) + packed sigmoid tanh (f16x2) ----
    float alpha[4], prod[4];
#pragma unroll
    for (int rr = 0; rr < 4; rr++) {
        const int p = rr * 32 + lane;
        float d = (p == 127) ? FARV : (zn[rr] - zp[rr]);
        d *= nrm;
        const float sg = fmaxf(rv[rr].w, 0.0f);
        const float ex = __expf(-sg * d);     // FMUL + MUFU.EX2 (f32: precision-critical)
        alpha[rr] = 1.0f - ex;
        prod[rr]  = ex + EPSV;                // t = 1 - alpha + EPS
    }

    // 6 packed tanh: channel c of rounds (2P, 2P+1) share one h2 op
    __half2 hs[6];
#pragma unroll
    for (int P = 0; P < 2; P++) {
        hs[P * 3 + 0] = h2_tanh(__floats2half2_rn(0.5f * rv[2 * P].x, 0.5f * rv[2 * P + 1].x));
        hs[P * 3 + 1] = h2_tanh(__floats2half2_rn(0.5f * rv[2 * P].y, 0.5f * rv[2 * P + 1].y));
        hs[P * 3 + 2] = h2_tanh(__floats2half2_rn(0.5f * rv[2 * P].z, 0.5f * rv[2 * P + 1].z));
    }

    // ---- Phase C: 4 interleaved inclusive product scans ----
#pragma unroll
    for (int off = 1; off < 32; off <<= 1) {
        const float v0 = __shfl_up_sync(FULL, prod[0], off);
        const float v1 = __shfl_up_sync(FULL, prod[1], off);
        const float v2 = __shfl_up_sync(FULL, prod[2], off);
        const float v3 = __shfl_up_sync(FULL, prod[3], off);
        if (lane >= off) {
            prod[0] *= v0; prod[1] *= v1; prod[2] *= v2; prod[3] *= v3;
        }
    }

    // round totals and carries (tiny serial combine)
    const float P0 = __shfl_sync(FULL, prod[0], 31);
    const float P1 = __shfl_sync(FULL, prod[1], 31);
    const float P2 = __shfl_sync(FULL, prod[2], 31);
    float carry[4];
    carry[0] = 1.0f;
    carry[1] = P0;
    carry[2] = P0 * P1;
    carry[3] = carry[2] * P2;

    // ---- Phase D: weights, unpack sigmoids, accumulate, store ----
    float ar = 0.f, ag = 0.f, ab = 0.f, aa = 0.f, ad = 0.f;
#pragma unroll
    for (int rr = 0; rr < 4; rr++) {
        float excl = __shfl_up_sync(FULL, prod[rr], 1);
        if (lane == 0) excl = 1.0f;
        const float w = alpha[rr] * (carry[rr] * excl);

        const int pair = rr >> 1;
        float t0, t1, t2;
        if ((rr & 1) == 0) {
            t0 = __low2float(hs[pair * 3 + 0]);
            t1 = __low2float(hs[pair * 3 + 1]);
            t2 = __low2float(hs[pair * 3 + 2]);
        } else {
            t0 = __high2float(hs[pair * 3 + 0]);
            t1 = __high2float(hs[pair * 3 + 1]);
            t2 = __high2float(hs[pair * 3 + 2]);
        }
        const float s0 = fmaf(0.5f, t0, 0.5f);
        const float s1 = fmaf(0.5f, t1, 0.5f);
        const float s2 = fmaf(0.5f, t2, 0.5f);

        ar = fmaf(w, s0, ar);
        ag = fmaf(w, s1, ag);
        ab = fmaf(w, s2, ab);
        aa += w;
        ad = fmaf(w, zp[rr], ad);

        out_w[(size_t)ray * 128 + rr * 32 + lane] = w;   // coalesced 128B store
    }

    // ---- warp tree-reduce the 5 scalars ----
#pragma unroll
    for (int off = 16; off >= 1; off >>= 1) {
        ar += __shfl_xor_sync(FULL, ar, off);
        ag += __shfl_xor_sync(FULL, ag, off);
        ab += __shfl_xor_sync(FULL, ab, off);
        aa += __shfl_xor_sync(FULL, aa, off);
        ad += __shfl_xor_sync(FULL, ad, off);
    }

    if (lane == 0) {
        const float b0 = bg[0], b1 = bg[1], b2 = bg[2];
        const bool is_bg = (b0 >= 0.f && b0 <= 1.f &&
                            b1 >= 0.f && b1 <= 1.f &&
                            b2 >= 0.f && b2 <= 1.f);
        if (is_bg) {
            const float m = 1.0f - aa;
            ar = fmaf(m, b0, ar);
            ag = fmaf(m, b1, ag);
            ab = fmaf(m, b2, ab);
        }
        out_rgb[ray * 3 + 0] = ar;
        out_rgb[ray * 3 + 1] = ag;
        out_rgb[ray * 3 + 2] = ab;
        out_depth[ray] = ad;
        out_alpha[ray] = aa;

        // disparity = 1 / (relu(depth/alpha - EPS) + EPS)  (precise divides; per-ray only)
        const float q = ad / aa;
        out_disp[ray] = 1.0f / (fmaxf(q - EPSV, 0.0f) + EPSV);
    }
}

extern "C" void kernel_launch(void* const* d_in, const int* in_sizes, int n_in,
                              void* d_out, int out_size)
{
    const float* raw = (const float*)d_in[0];  // (B,R,P,4)
    const float* zv  = (const float*)d_in[1];  // (B,R,P)
    const float* rd  = (const float*)d_in[2];  // (B,R,3)
    const float* bg  = (const float*)d_in[3];  // (3)

    const int nrays = in_sizes[1] / 128;       // B*R

    float* out       = (float*)d_out;
    float* out_rgb   = out;
    float* out_depth = out + (size_t)nrays * 3;
    float* out_disp  = out + (size_t)nrays * 4;
    float* out_alpha = out + (size_t)nrays * 5;
    float* out_w     = out + (size_t)nrays * 6;

    const int blocks = (nrays + 7) / 8;        // 8 warps (rays) per 256-thread block
    nerf_agg_kernel<<<blocks, 256>>>((const float4*)raw, zv, rd, bg,
                                     out_rgb, out_depth, out_disp, out_alpha,
                                     out_w, nrays);
}

// round 5
// speedup vs baseline: 1.0175x; 1.0175x over previous
#include <cuda_runtime.h>
#include <cuda_fp16.h>

// NeRF volume-rendering aggregation — R5.
// Ownership flip: each lane owns 4 CONSECUTIVE points (p = lane*4+i).
//  - ONE warp product-scan (6 SHFL) instead of 4 interleaved scans (27 SHFL)
//  - z: single coalesced LDG.128; z[p+1] lane-local except 1 shfl_down
//  - weights: single STG.128
//  - raw float4s transposed through per-warp SMEM (swizzled, conflict-free)
// Sigmoids stay tanh.approx.f16x2; alpha exp stays f32.

#define FARV 1e10f
#define EPSV 1e-10f
#define FULL 0xffffffffu

__device__ __forceinline__ __half2 h2_tanh(__half2 x) {
    __half2 r;
    asm("tanh.approx.f16x2 %0, %1;" : "=r"(*(unsigned*)&r) : "r"(*(unsigned*)&x));
    return r;
}

// XOR-swizzle byte address within a 2048B tile: folds addr bits [8:7] into [5:4].
// Makes both stride-16B writes and stride-64B float4 reads bank-conflict-free.
__device__ __forceinline__ unsigned swz(unsigned a) {
    return a ^ ((a >> 3) & 0x30u);
}

__global__ __launch_bounds__(256) void nerf_agg_kernel(
    const float4* __restrict__ raw,    // (NR, 128) of float4
    const float*  __restrict__ z,      // (NR, 128)
    const float*  __restrict__ rays_d, // (NR, 3)
    const float*  __restrict__ bg,     // (3)
    float* __restrict__ out_rgb,       // (NR, 3)
    float* __restrict__ out_depth,     // (NR)
    float* __restrict__ out_disp,      // (NR)
    float* __restrict__ out_alpha,     // (NR)
    float* __restrict__ out_w,         // (NR, 128)
    int nrays)
{
    __shared__ char sbuf[8 * 2048];    // per-warp 128-point float4 staging tile

    const int warp = threadIdx.x >> 5;
    const int lane = threadIdx.x & 31;
    const int ray  = blockIdx.x * 8 + warp;
    if (ray >= nrays) return;          // warp-uniform exit

    char* sw = sbuf + warp * 2048;
    const float4* rawr = raw + (size_t)ray * 128;

    // ---- coalesced loads ----
    float4 rv0 = rawr[lane];
    float4 rv1 = rawr[32 + lane];
    float4 rv2 = rawr[64 + lane];
    float4 rv3 = rawr[96 + lane];
    const float4 z4 = *(const float4*)(z + (size_t)ray * 128 + lane * 4);

    // ray-direction norm (lane-uniform broadcast loads)
    const float dx = rays_d[ray * 3 + 0];
    const float dy = rays_d[ray * 3 + 1];
    const float dz = rays_d[ray * 3 + 2];
    const float nrm = sqrtf(dx * dx + dy * dy + dz * dz);

    // ---- transpose raw through SMEM: write point (rr*32+lane), read (lane*4+i) ----
    *(float4*)(sw + swz((lane       ) * 16u)) = rv0;
    *(float4*)(sw + swz((32  + lane ) * 16u)) = rv1;
    *(float4*)(sw + swz((64  + lane ) * 16u)) = rv2;
    *(float4*)(sw + swz((96  + lane ) * 16u)) = rv3;
    __syncwarp();
    float4 pt[4];
#pragma unroll
    for (int i = 0; i < 4; i++)
        pt[i] = *(const float4*)(sw + swz((lane * 4 + i) * 16u));

    // ---- z neighbors: lane-local except the lane boundary ----
    const float zn3 = __shfl_down_sync(FULL, z4.x, 1);   // z[lane*4+4]
    const float zloc[4] = { z4.x, z4.y, z4.z, z4.w };
    const float znxt[4] = { z4.y, z4.z, z4.w, zn3 };

    // ---- alpha + transmittance factors (f32 EX2) ----
    float alpha[4], t[4];
#pragma unroll
    for (int i = 0; i < 4; i++) {
        float d = znxt[i] - zloc[i];
        if (i == 3 && lane == 31) d = FARV;              // p == 127
        d *= nrm;
        const float ex = __expf(-fmaxf(pt[i].w, 0.0f) * d);
        alpha[i] = 1.0f - ex;
        t[i]     = ex + EPSV;                            // 1 - alpha + EPS
    }

    // ---- single warp scan over local products ----
    const float L = (t[0] * t[1]) * (t[2] * t[3]);
    float S = L;
#pragma unroll
    for (int off = 1; off < 32; off <<= 1) {
        const float v = __shfl_up_sync(FULL, S, off);
        S = (lane >= off) ? S * v : S;
    }
    float E = __shfl_up_sync(FULL, S, 1);                // exclusive lane prefix
    if (lane == 0) E = 1.0f;

    // per-point exclusive prefixes + weights
    const float e1 = E  * t[0];
    const float e2 = e1 * t[1];
    const float e3 = e2 * t[2];
    const float w0 = alpha[0] * E;
    const float w1 = alpha[1] * e1;
    const float w2 = alpha[2] * e2;
    const float w3 = alpha[3] * e3;

    // single vectorized weights store
    *(float4*)(out_w + (size_t)ray * 128 + lane * 4) = make_float4(w0, w1, w2, w3);

    // ---- packed sigmoids: pairs (0,1) and (2,3) per channel ----
    const __half2 hx0 = h2_tanh(__floats2half2_rn(0.5f * pt[0].x, 0.5f * pt[1].x));
    const __half2 hy0 = h2_tanh(__floats2half2_rn(0.5f * pt[0].y, 0.5f * pt[1].y));
    const __half2 hz0 = h2_tanh(__floats2half2_rn(0.5f * pt[0].z, 0.5f * pt[1].z));
    const __half2 hx1 = h2_tanh(__floats2half2_rn(0.5f * pt[2].x, 0.5f * pt[3].x));
    const __half2 hy1 = h2_tanh(__floats2half2_rn(0.5f * pt[2].y, 0.5f * pt[3].y));
    const __half2 hz1 = h2_tanh(__floats2half2_rn(0.5f * pt[2].z, 0.5f * pt[3].z));

    // sigma(x) = 0.5*tanh(0.5x)+0.5 ; accumulate w-weighted
    float ar, ag, ab, aa, ad;
    ar = w0 * fmaf(0.5f, __low2float (hx0), 0.5f)
       + w1 * fmaf(0.5f, __high2float(hx0), 0.5f)
       + w2 * fmaf(0.5f, __low2float (hx1), 0.5f)
       + w3 * fmaf(0.5f, __high2float(hx1), 0.5f);
    ag = w0 * fmaf(0.5f, __low2float (hy0), 0.5f)
       + w1 * fmaf(0.5f, __high2float(hy0), 0.5f)
       + w2 * fmaf(0.5f, __low2float (hy1), 0.5f)
       + w3 * fmaf(0.5f, __high2float(hy1), 0.5f);
    ab = w0 * fmaf(0.5f, __low2float (hz0), 0.5f)
       + w1 * fmaf(0.5f, __high2float(hz0), 0.5f)
       + w2 * fmaf(0.5f, __low2float (hz1), 0.5f)
       + w3 * fmaf(0.5f, __high2float(hz1), 0.5f);
    aa = (w0 + w1) + (w2 + w3);
    ad = fmaf(w0, zloc[0], fmaf(w1, zloc[1], fmaf(w2, zloc[2], w3 * zloc[3])));

    // ---- warp tree-reduce the 5 scalars ----
#pragma unroll
    for (int off = 16; off >= 1; off >>= 1) {
        ar += __shfl_xor_sync(FULL, ar, off);
        ag += __shfl_xor_sync(FULL, ag, off);
        ab += __shfl_xor_sync(FULL, ab, off);
        aa += __shfl_xor_sync(FULL, aa, off);
        ad += __shfl_xor_sync(FULL, ad, off);
    }

    if (lane == 0) {
        const float b0 = bg[0], b1 = bg[1], b2 = bg[2];
        const bool is_bg = (b0 >= 0.f && b0 <= 1.f &&
                            b1 >= 0.f && b1 <= 1.f &&
                            b2 >= 0.f && b2 <= 1.f);
        if (is_bg) {
            const float m = 1.0f - aa;
            ar = fmaf(m, b0, ar);
            ag = fmaf(m, b1, ag);
            ab = fmaf(m, b2, ab);
        }
        out_rgb[ray * 3 + 0] = ar;
        out_rgb[ray * 3 + 1] = ag;
        out_rgb[ray * 3 + 2] = ab;
        out_depth[ray] = ad;
        out_alpha[ray] = aa;

        // disparity = 1 / (relu(depth/alpha - EPS) + EPS)
        const float q = ad / aa;
        out_disp[ray] = 1.0f / (fmaxf(q - EPSV, 0.0f) + EPSV);
    }
}

extern "C" void kernel_launch(void* const* d_in, const int* in_sizes, int n_in,
                              void* d_out, int out_size)
{
    const float* raw = (const float*)d_in[0];  // (B,R,P,4)
    const float* zv  = (const float*)d_in[1];  // (B,R,P)
    const float* rd  = (const float*)d_in[2];  // (B,R,3)
    const float* bg  = (const float*)d_in[3];  // (3)

    const int nrays = in_sizes[1] / 128;       // B*R

    float* out       = (float*)d_out;
    float* out_rgb   = out;
    float* out_depth = out + (size_t)nrays * 3;
    float* out_disp  = out + (size_t)nrays * 4;
    float* out_alpha = out + (size_t)nrays * 5;
    float* out_w     = out + (size_t)nrays * 6;

    const int blocks = (nrays + 7) / 8;        // 8 warps (rays) per 256-thread block
    nerf_agg_kernel<<<blocks, 256>>>((const float4*)raw, zv, rd, bg,
                                     out_rgb, out_depth, out_disp, out_alpha,
                                     out_w, nrays);
}